// round 2
// baseline (speedup 1.0000x reference)
#include <cuda_runtime.h>
#include <cstdint>

// ---------------- problem constants ----------------
#define NN   65536      // base nodes
#define MM   65536      // local nodes
#define HH   128        // hidden / feature dim
#define BB   64         // groups
#define OUTD 2
#define ALPHA 0.9f

// ---------------- device scratch (no runtime allocation allowed) ----------------
__device__ float g_base_x  [(size_t)NN * HH];
__device__ float g_base_agg[(size_t)NN * HH];
__device__ float g_local_x [(size_t)MM * HH];
__device__ float g_local_agg[(size_t)MM * HH];
__device__ float g_sub[BB * HH];
__device__ float g_cnt[BB];

// ---------------- GEMM: C[R x128] = relu(A'[R x128] @ W[128x128] + bias) ----------------
// A' = A                      (MIX=false)
// A' = ALPHA*A + (1-ALPHA)*BX[c2o[row]]   (MIX=true, fused alpha-mix)
//
// block: 256 threads, 128 rows x 128 cols per block, 8x8 microtile per thread.
// Math uses packed fma.rn.f32x2 (FFMA2): 32 FFMA2 per thread per k instead of
// 64 scalar FFMA. To avoid packing MOVs:
//   - As is [k][row] (padded), so row pairs (tr,tr+1) are natural b64 pairs.
//   - W is staged in smem duplicated: Wdup[k][j] = (w,w) as 64-bit.
#define AS_LD 132
#define GEMM_SMEM (128 * AS_LD * 4 + 128 * 128 * 8)   // 67584 + 131072 = 198656 B

__device__ __forceinline__ void ffma2(unsigned long long& d,
                                      unsigned long long a,
                                      unsigned long long b)
{
    asm("fma.rn.f32x2 %0, %1, %2, %0;" : "+l"(d) : "l"(a), "l"(b));
}

__device__ __forceinline__ unsigned long long dup2(float x)
{
    float2 t = make_float2(x, x);
    return *(unsigned long long*)&t;
}

template<bool MIX>
__global__ void __launch_bounds__(256, 1)
gemm128_bias_relu(const float* __restrict__ A,
                  const float* __restrict__ W,
                  const float* __restrict__ bias,
                  float* __restrict__ C,
                  const float* __restrict__ BX,
                  const int* __restrict__ c2o)
{
    extern __shared__ float smem[];
    float*              As   = smem;                              // [128][AS_LD]
    unsigned long long* Wdup = (unsigned long long*)(smem + 128 * AS_LD); // [128][128] dup pairs

    const int tid  = threadIdx.x;
    const int row0 = blockIdx.x * 128;

    // ---- stage W duplicated into Wdup ----
    {
        const float4* W4 = (const float4*)W;
        #pragma unroll
        for (int i = 0; i < 16; i++) {
            int idx = tid + 256 * i;           // float4 index, covers floats 4idx..4idx+3
            float4 v = W4[idx];
            ulonglong2 d0, d1;
            d0.x = dup2(v.x); d0.y = dup2(v.y);
            d1.x = dup2(v.z); d1.y = dup2(v.w);
            *(ulonglong2*)&Wdup[4 * idx]     = d0;
            *(ulonglong2*)&Wdup[4 * idx + 2] = d1;
        }
    }
    // ---- stage A tile transposed into As[k][row] (optionally fused alpha-mix) ----
    {
        const float4* A4 = (const float4*)(A + (size_t)row0 * HH);
        #pragma unroll
        for (int i = 0; i < 16; i++) {
            int idx = tid + 256 * i;      // = r*32 + k4  (per warp: one row, lanes = k4)
            int r   = idx >> 5;
            int k4  = idx & 31;
            float4 v = A4[idx];
            if (MIX) {
                int o = __ldg(&c2o[row0 + r]);
                float4 b = *(const float4*)&BX[(size_t)o * HH + k4 * 4];
                v.x = ALPHA * v.x + (1.0f - ALPHA) * b.x;
                v.y = ALPHA * v.y + (1.0f - ALPHA) * b.y;
                v.z = ALPHA * v.z + (1.0f - ALPHA) * b.z;
                v.w = ALPHA * v.w + (1.0f - ALPHA) * b.w;
            }
            As[(4 * k4 + 0) * AS_LD + r] = v.x;
            As[(4 * k4 + 1) * AS_LD + r] = v.y;
            As[(4 * k4 + 2) * AS_LD + r] = v.z;
            As[(4 * k4 + 3) * AS_LD + r] = v.w;
        }
    }
    __syncthreads();

    const int tr = (tid >> 4) * 8;   // row offset in tile (even, 0..120)
    const int tc = (tid & 15) * 8;   // col offset in tile (0..120)

    unsigned long long acc2[4][8];   // acc2[ip][j] = (C[tr+2ip][tc+j], C[tr+2ip+1][tc+j])
    #pragma unroll
    for (int ip = 0; ip < 4; ip++)
        #pragma unroll
        for (int j = 0; j < 8; j++) acc2[ip][j] = 0ull;

    #pragma unroll 4
    for (int k = 0; k < 128; k++) {
        ulonglong2 aA = *(const ulonglong2*)&As[k * AS_LD + tr];      // rows (tr,tr+1),(tr+2,tr+3)
        ulonglong2 aB = *(const ulonglong2*)&As[k * AS_LD + tr + 4];  // rows (tr+4..tr+7)
        ulonglong2 w0 = *(const ulonglong2*)&Wdup[k * 128 + tc];
        ulonglong2 w1 = *(const ulonglong2*)&Wdup[k * 128 + tc + 2];
        ulonglong2 w2 = *(const ulonglong2*)&Wdup[k * 128 + tc + 4];
        ulonglong2 w3 = *(const ulonglong2*)&Wdup[k * 128 + tc + 6];
        unsigned long long a2[4] = {aA.x, aA.y, aB.x, aB.y};
        unsigned long long wv[8] = {w0.x, w0.y, w1.x, w1.y, w2.x, w2.y, w3.x, w3.y};
        #pragma unroll
        for (int ip = 0; ip < 4; ip++)
            #pragma unroll
            for (int j = 0; j < 8; j++)
                ffma2(acc2[ip][j], a2[ip], wv[j]);
    }

    float bv[8];
    *(float4*)&bv[0] = *(const float4*)&bias[tc];
    *(float4*)&bv[4] = *(const float4*)&bias[tc + 4];

    #pragma unroll
    for (int ip = 0; ip < 4; ip++) {
        float lo[8], hi[8];
        #pragma unroll
        for (int j = 0; j < 8; j++) {
            float2 f = *(float2*)&acc2[ip][j];
            lo[j] = fmaxf(f.x + bv[j], 0.f);
            hi[j] = fmaxf(f.y + bv[j], 0.f);
        }
        float* cp0 = &C[(size_t)(row0 + tr + 2 * ip)     * HH + tc];
        float* cp1 = &C[(size_t)(row0 + tr + 2 * ip + 1) * HH + tc];
        ((float4*)cp0)[0] = make_float4(lo[0], lo[1], lo[2], lo[3]);
        ((float4*)cp0)[1] = make_float4(lo[4], lo[5], lo[6], lo[7]);
        ((float4*)cp1)[0] = make_float4(hi[0], hi[1], hi[2], hi[3]);
        ((float4*)cp1)[1] = make_float4(hi[4], hi[5], hi[6], hi[7]);
    }
}

// ---------------- SpMM scatter: Y[dst] += w * X[src], warp per edge ----------------
__global__ void spmm_atomic(const float* __restrict__ X,
                            const int* __restrict__ src,
                            const int* __restrict__ dst,
                            const float* __restrict__ wgt,
                            float* __restrict__ Y, int E)
{
    const int lane   = threadIdx.x & 31;
    const int warp   = (blockIdx.x * blockDim.x + threadIdx.x) >> 5;
    const int nwarps = (gridDim.x * blockDim.x) >> 5;
    for (int e = warp; e < E; e += nwarps) {
        int   s = src[e];
        int   d = dst[e];
        float w = wgt[e];
        float4 v = *(const float4*)&X[(size_t)s * HH + lane * 4];
        v.x *= w; v.y *= w; v.z *= w; v.w *= w;
        float* p = &Y[(size_t)d * HH + lane * 4];
        asm volatile("red.global.add.v4.f32 [%0], {%1, %2, %3, %4};"
                     :: "l"(p), "f"(v.x), "f"(v.y), "f"(v.z), "f"(v.w)
                     : "memory");
    }
}

// ---------------- pooling: two-stage segment-sum into g_sub / g_cnt ----------------
__global__ void pool_kernel(const float* __restrict__ lx,
                            const int* __restrict__ midx,
                            const int* __restrict__ mgid,
                            float* __restrict__ gsub,
                            float* __restrict__ gcnt,
                            int K, int entries_per_block)
{
    __shared__ float acc[BB * HH];   // 32 KB
    __shared__ float cnt[BB];
    const int tid = threadIdx.x;
    for (int i = tid; i < BB * HH; i += blockDim.x) acc[i] = 0.f;
    if (tid < BB) cnt[tid] = 0.f;
    __syncthreads();

    const int warp = tid >> 5;
    const int lane = tid & 31;
    const int base = blockIdx.x * entries_per_block;
    const int end  = min(base + entries_per_block, K);
    for (int k = base + warp; k < end; k += (int)(blockDim.x >> 5)) {
        int idx = midx[k];
        int g   = mgid[k];
        float4 v = *(const float4*)&lx[(size_t)idx * HH + lane * 4];
        atomicAdd(&acc[g * HH + lane * 4 + 0], v.x);
        atomicAdd(&acc[g * HH + lane * 4 + 1], v.y);
        atomicAdd(&acc[g * HH + lane * 4 + 2], v.z);
        atomicAdd(&acc[g * HH + lane * 4 + 3], v.w);
        if (lane == 0) atomicAdd(&cnt[g], 1.f);
    }
    __syncthreads();

    for (int i = tid; i < BB * HH; i += blockDim.x)
        if (acc[i] != 0.f) atomicAdd(&gsub[i], acc[i]);
    if (tid < BB && cnt[tid] != 0.f) atomicAdd(&gcnt[tid], cnt[tid]);
}

// ---------------- final: out[b][o] = (sub[b]/max(cnt,1)) @ Wp + bp ----------------
__global__ void final_kernel(const float* __restrict__ gsub,
                             const float* __restrict__ gcnt,
                             const float* __restrict__ Wp,
                             const float* __restrict__ bp,
                             float* __restrict__ out)
{
    int t = threadIdx.x;                 // 0..127
    if (t >= BB * OUTD) return;
    int b = t >> 1, o = t & 1;
    float c = fmaxf(gcnt[b], 1.f);
    float s = 0.f;
    #pragma unroll 8
    for (int h = 0; h < HH; h++) s = fmaf(gsub[b * HH + h], Wp[h * OUTD + o], s);
    out[t] = s / c + bp[o];
}

// ---------------- host orchestration ----------------
extern "C" void kernel_launch(void* const* d_in, const int* in_sizes, int n_in,
                              void* d_out, int out_size)
{
    const float* x    = (const float*)d_in[0];
    const int*   ei   = (const int*)  d_in[1];
    const float* ew   = (const float*)d_in[2];
    const float* lx0  = (const float*)d_in[3];
    const int*   c2o  = (const int*)  d_in[4];
    const int*   lei  = (const int*)  d_in[5];
    const float* lev  = (const float*)d_in[6];
    const int*   midx = (const int*)  d_in[7];
    const int*   mgid = (const int*)  d_in[8];
    // d_in[9] = B (scalar) -- fixed at 64
    const float* Wb    = (const float*)d_in[10];
    const float* bb    = (const float*)d_in[11];
    const float* Wl    = (const float*)d_in[12];
    const float* bl    = (const float*)d_in[13];
    const float* Wbase = (const float*)d_in[14];
    const float* bbase = (const float*)d_in[15];
    const float* Wloc  = (const float*)d_in[16];
    const float* bloc  = (const float*)d_in[17];
    const float* Wp    = (const float*)d_in[18];
    const float* bp    = (const float*)d_in[19];
    float* out = (float*)d_out;

    const int N  = in_sizes[0] / HH;
    const int M  = in_sizes[3] / HH;
    const int E  = in_sizes[1] / 2;
    const int EL = in_sizes[5] / 2;
    const int K  = in_sizes[7];
    const int L  = in_sizes[14] / (HH * HH);

    float *base_x, *base_agg, *local_x, *local_agg, *sub, *cntp;
    cudaGetSymbolAddress((void**)&base_x,   g_base_x);
    cudaGetSymbolAddress((void**)&base_agg, g_base_agg);
    cudaGetSymbolAddress((void**)&local_x,  g_local_x);
    cudaGetSymbolAddress((void**)&local_agg,g_local_agg);
    cudaGetSymbolAddress((void**)&sub,      g_sub);
    cudaGetSymbolAddress((void**)&cntp,     g_cnt);

    cudaFuncSetAttribute(gemm128_bias_relu<false>,
                         cudaFuncAttributeMaxDynamicSharedMemorySize, GEMM_SMEM);
    cudaFuncSetAttribute(gemm128_bias_relu<true>,
                         cudaFuncAttributeMaxDynamicSharedMemorySize, GEMM_SMEM);

    const int gemm_blocks_N = N / 128;
    const int gemm_blocks_M = M / 128;

    // input projections
    gemm128_bias_relu<false><<<gemm_blocks_N, 256, GEMM_SMEM>>>(
        x,   Wb, bb, base_x, nullptr, nullptr);
    gemm128_bias_relu<false><<<gemm_blocks_M, 256, GEMM_SMEM>>>(
        lx0, Wl, bl, local_x, nullptr, nullptr);

    const int spmm_blocks = 4096;

    for (int l = 0; l < L; l++) {
        // base graph propagation
        cudaMemsetAsync(base_agg, 0, (size_t)N * HH * sizeof(float));
        spmm_atomic<<<spmm_blocks, 256>>>(base_x, ei, ei + E, ew, base_agg, E);
        gemm128_bias_relu<false><<<gemm_blocks_N, 256, GEMM_SMEM>>>(
            base_agg, Wbase + (size_t)l * HH * HH, bbase + (size_t)l * HH, base_x,
            nullptr, nullptr);

        // local union-graph propagation + fused alpha-mix GEMM
        cudaMemsetAsync(local_agg, 0, (size_t)M * HH * sizeof(float));
        spmm_atomic<<<spmm_blocks, 256>>>(local_x, lei, lei + EL, lev, local_agg, EL);
        gemm128_bias_relu<true><<<gemm_blocks_M, 256, GEMM_SMEM>>>(
            local_agg, Wloc + (size_t)l * HH * HH, bloc + (size_t)l * HH, local_x,
            base_x, c2o);
    }

    // scatter-mean pooling + final projection
    cudaMemsetAsync(sub,  0, BB * HH * sizeof(float));
    cudaMemsetAsync(cntp, 0, BB * sizeof(float));
    const int pool_blocks = 128;
    const int entries_per_block = (K + pool_blocks - 1) / pool_blocks;
    pool_kernel<<<pool_blocks, 256>>>(local_x, midx, mgid, sub, cntp, K, entries_per_block);
    final_kernel<<<1, 128>>>(sub, cntp, Wp, bp, out);
}

// round 3
// speedup vs baseline: 1.3567x; 1.3567x over previous
#include <cuda_runtime.h>
#include <cstdint>

// ---------------- problem constants ----------------
#define NN   65536      // base nodes
#define MM   65536      // local nodes
#define HH   128        // hidden / feature dim
#define BB   64         // groups
#define OUTD 2
#define ALPHA 0.9f

// ---------------- device scratch (no runtime allocation allowed) ----------------
__device__ float g_base_x  [(size_t)NN * HH];
__device__ float g_base_agg[(size_t)NN * HH];
__device__ float g_local_x [(size_t)MM * HH];
__device__ float g_local_agg[(size_t)MM * HH];
__device__ float g_sub[BB * HH];
__device__ float g_cnt[BB];

// ---------------- GEMM: C[R x128] = relu(A'[R x128] @ W[128x128] + bias) ----------------
// A' = A                                   (MIX=false)
// A' = ALPHA*A + (1-ALPHA)*BX[c2o[row]]    (MIX=true, fused alpha-mix)
//
// 512 threads, 128x128 tile, 4x8 microtile. Math = packed fma.rn.f32x2.
// Smem layouts identical to the round-1 (known conflict-OK) version:
//   As[k][row] padded to 132, Ws[k][col] dense floats.
// W pairs (w_{2j}, w_{2j+1}) come directly from LDS.128 register pairs.
// A is duplicated in registers with one mov.b64 {r,r} per value.
#define AS_LD 132
#define GEMM_SMEM ((128 * AS_LD + 128 * 128) * sizeof(float))   // 133120 B

__device__ __forceinline__ void ffma2(unsigned long long& d,
                                      unsigned long long a,
                                      unsigned long long b)
{
    asm("fma.rn.f32x2 %0, %1, %2, %0;" : "+l"(d) : "l"(a), "l"(b));
}

__device__ __forceinline__ unsigned long long dup_reg(float x)
{
    unsigned long long r;
    asm("mov.b64 %0, {%1, %1};" : "=l"(r) : "r"(__float_as_uint(x)));
    return r;
}

template<bool MIX>
__global__ void __launch_bounds__(512, 1)
gemm128_bias_relu(const float* __restrict__ A,
                  const float* __restrict__ W,
                  const float* __restrict__ bias,
                  float* __restrict__ C,
                  const float* __restrict__ BX,
                  const int* __restrict__ c2o)
{
    extern __shared__ float smem[];
    float* As = smem;                 // [128][AS_LD]  As[k][row]
    float* Ws = smem + 128 * AS_LD;   // [128][128]    Ws[k][col]

    const int tid  = threadIdx.x;
    const int row0 = blockIdx.x * 128;

    // ---- stage W (16384 floats), 8 float4 per thread, coalesced ----
    {
        const float4* W4  = (const float4*)W;
        float4*       Ws4 = (float4*)Ws;
        #pragma unroll
        for (int i = 0; i < 8; i++) Ws4[tid + 512 * i] = W4[tid + 512 * i];
    }
    // ---- stage A tile transposed into As[k][row] (optional fused alpha-mix) ----
    {
        const float4* A4 = (const float4*)(A + (size_t)row0 * HH);
        #pragma unroll
        for (int i = 0; i < 8; i++) {
            int idx = tid + 512 * i;      // = r*32 + k4 (warp: one row, lanes = k4)
            int r   = idx >> 5;
            int k4  = idx & 31;
            float4 v = A4[idx];
            if (MIX) {
                int o = __ldg(&c2o[row0 + r]);
                float4 b = *(const float4*)&BX[(size_t)o * HH + k4 * 4];
                v.x = ALPHA * v.x + (1.0f - ALPHA) * b.x;
                v.y = ALPHA * v.y + (1.0f - ALPHA) * b.y;
                v.z = ALPHA * v.z + (1.0f - ALPHA) * b.z;
                v.w = ALPHA * v.w + (1.0f - ALPHA) * b.w;
            }
            As[(4 * k4 + 0) * AS_LD + r] = v.x;
            As[(4 * k4 + 1) * AS_LD + r] = v.y;
            As[(4 * k4 + 2) * AS_LD + r] = v.z;
            As[(4 * k4 + 3) * AS_LD + r] = v.w;
        }
    }
    __syncthreads();

    const int tc = (tid & 15) * 8;    // col offset (0..120)
    const int tr = (tid >> 4) * 4;    // row offset (0..124)

    // acc2[i][jp] = (C[tr+i][tc+2jp], C[tr+i][tc+2jp+1])
    unsigned long long acc2[4][4];
    #pragma unroll
    for (int i = 0; i < 4; i++)
        #pragma unroll
        for (int jp = 0; jp < 4; jp++) acc2[i][jp] = 0ull;

    #pragma unroll 4
    for (int k = 0; k < 128; k++) {
        float4 av = *(const float4*)&As[k * AS_LD + tr];           // rows tr..tr+3
        // natural column pairs straight out of the float4 register quads
        ulonglong2 wp0 = *(const ulonglong2*)&Ws[k * 128 + tc];      // (w0,w1),(w2,w3)
        ulonglong2 wp1 = *(const ulonglong2*)&Ws[k * 128 + tc + 4];  // (w4,w5),(w6,w7)
        unsigned long long a2[4];
        a2[0] = dup_reg(av.x);
        a2[1] = dup_reg(av.y);
        a2[2] = dup_reg(av.z);
        a2[3] = dup_reg(av.w);
        unsigned long long wv[4] = {wp0.x, wp0.y, wp1.x, wp1.y};
        #pragma unroll
        for (int i = 0; i < 4; i++)
            #pragma unroll
            for (int jp = 0; jp < 4; jp++)
                ffma2(acc2[i][jp], a2[i], wv[jp]);
    }

    float bv[8];
    *(float4*)&bv[0] = *(const float4*)&bias[tc];
    *(float4*)&bv[4] = *(const float4*)&bias[tc + 4];

    #pragma unroll
    for (int i = 0; i < 4; i++) {
        float c[8];
        #pragma unroll
        for (int jp = 0; jp < 4; jp++) {
            float2 f = *(float2*)&acc2[i][jp];
            c[2 * jp]     = fmaxf(f.x + bv[2 * jp],     0.f);
            c[2 * jp + 1] = fmaxf(f.y + bv[2 * jp + 1], 0.f);
        }
        float* cp = &C[(size_t)(row0 + tr + i) * HH + tc];
        ((float4*)cp)[0] = make_float4(c[0], c[1], c[2], c[3]);
        ((float4*)cp)[1] = make_float4(c[4], c[5], c[6], c[7]);
    }
}

// ---------------- SpMM scatter: Y[dst] += w * X[src], warp per edge ----------------
__global__ void spmm_atomic(const float* __restrict__ X,
                            const int* __restrict__ src,
                            const int* __restrict__ dst,
                            const float* __restrict__ wgt,
                            float* __restrict__ Y, int E)
{
    const int lane   = threadIdx.x & 31;
    const int warp   = (blockIdx.x * blockDim.x + threadIdx.x) >> 5;
    const int nwarps = (gridDim.x * blockDim.x) >> 5;
    for (int e = warp; e < E; e += nwarps) {
        int   s = src[e];
        int   d = dst[e];
        float w = wgt[e];
        float4 v = *(const float4*)&X[(size_t)s * HH + lane * 4];
        v.x *= w; v.y *= w; v.z *= w; v.w *= w;
        float* p = &Y[(size_t)d * HH + lane * 4];
        asm volatile("red.global.add.v4.f32 [%0], {%1, %2, %3, %4};"
                     :: "l"(p), "f"(v.x), "f"(v.y), "f"(v.z), "f"(v.w)
                     : "memory");
    }
}

// ---------------- pooling: two-stage segment-sum into g_sub / g_cnt ----------------
__global__ void pool_kernel(const float* __restrict__ lx,
                            const int* __restrict__ midx,
                            const int* __restrict__ mgid,
                            float* __restrict__ gsub,
                            float* __restrict__ gcnt,
                            int K, int entries_per_block)
{
    __shared__ float acc[BB * HH];   // 32 KB
    __shared__ float cnt[BB];
    const int tid = threadIdx.x;
    for (int i = tid; i < BB * HH; i += blockDim.x) acc[i] = 0.f;
    if (tid < BB) cnt[tid] = 0.f;
    __syncthreads();

    const int warp = tid >> 5;
    const int lane = tid & 31;
    const int base = blockIdx.x * entries_per_block;
    const int end  = min(base + entries_per_block, K);
    for (int k = base + warp; k < end; k += (int)(blockDim.x >> 5)) {
        int idx = midx[k];
        int g   = mgid[k];
        float4 v = *(const float4*)&lx[(size_t)idx * HH + lane * 4];
        atomicAdd(&acc[g * HH + lane * 4 + 0], v.x);
        atomicAdd(&acc[g * HH + lane * 4 + 1], v.y);
        atomicAdd(&acc[g * HH + lane * 4 + 2], v.z);
        atomicAdd(&acc[g * HH + lane * 4 + 3], v.w);
        if (lane == 0) atomicAdd(&cnt[g], 1.f);
    }
    __syncthreads();

    for (int i = tid; i < BB * HH; i += blockDim.x)
        if (acc[i] != 0.f) atomicAdd(&gsub[i], acc[i]);
    if (tid < BB && cnt[tid] != 0.f) atomicAdd(&gcnt[tid], cnt[tid]);
}

// ---------------- final: out[b][o] = (sub[b]/max(cnt,1)) @ Wp + bp ----------------
__global__ void final_kernel(const float* __restrict__ gsub,
                             const float* __restrict__ gcnt,
                             const float* __restrict__ Wp,
                             const float* __restrict__ bp,
                             float* __restrict__ out)
{
    int t = threadIdx.x;                 // 0..127
    if (t >= BB * OUTD) return;
    int b = t >> 1, o = t & 1;
    float c = fmaxf(gcnt[b], 1.f);
    float s = 0.f;
    #pragma unroll 8
    for (int h = 0; h < HH; h++) s = fmaf(gsub[b * HH + h], Wp[h * OUTD + o], s);
    out[t] = s / c + bp[o];
}

// ---------------- host orchestration ----------------
extern "C" void kernel_launch(void* const* d_in, const int* in_sizes, int n_in,
                              void* d_out, int out_size)
{
    const float* x    = (const float*)d_in[0];
    const int*   ei   = (const int*)  d_in[1];
    const float* ew   = (const float*)d_in[2];
    const float* lx0  = (const float*)d_in[3];
    const int*   c2o  = (const int*)  d_in[4];
    const int*   lei  = (const int*)  d_in[5];
    const float* lev  = (const float*)d_in[6];
    const int*   midx = (const int*)  d_in[7];
    const int*   mgid = (const int*)  d_in[8];
    // d_in[9] = B (scalar) -- fixed at 64
    const float* Wb    = (const float*)d_in[10];
    const float* bb    = (const float*)d_in[11];
    const float* Wl    = (const float*)d_in[12];
    const float* bl    = (const float*)d_in[13];
    const float* Wbase = (const float*)d_in[14];
    const float* bbase = (const float*)d_in[15];
    const float* Wloc  = (const float*)d_in[16];
    const float* bloc  = (const float*)d_in[17];
    const float* Wp    = (const float*)d_in[18];
    const float* bp    = (const float*)d_in[19];
    float* out = (float*)d_out;

    const int N  = in_sizes[0] / HH;
    const int M  = in_sizes[3] / HH;
    const int E  = in_sizes[1] / 2;
    const int EL = in_sizes[5] / 2;
    const int K  = in_sizes[7];
    const int L  = in_sizes[14] / (HH * HH);

    float *base_x, *base_agg, *local_x, *local_agg, *sub, *cntp;
    cudaGetSymbolAddress((void**)&base_x,   g_base_x);
    cudaGetSymbolAddress((void**)&base_agg, g_base_agg);
    cudaGetSymbolAddress((void**)&local_x,  g_local_x);
    cudaGetSymbolAddress((void**)&local_agg,g_local_agg);
    cudaGetSymbolAddress((void**)&sub,      g_sub);
    cudaGetSymbolAddress((void**)&cntp,     g_cnt);

    cudaFuncSetAttribute(gemm128_bias_relu<false>,
                         cudaFuncAttributeMaxDynamicSharedMemorySize, (int)GEMM_SMEM);
    cudaFuncSetAttribute(gemm128_bias_relu<true>,
                         cudaFuncAttributeMaxDynamicSharedMemorySize, (int)GEMM_SMEM);

    const int gemm_blocks_N = N / 128;
    const int gemm_blocks_M = M / 128;

    // input projections
    gemm128_bias_relu<false><<<gemm_blocks_N, 512, GEMM_SMEM>>>(
        x,   Wb, bb, base_x, nullptr, nullptr);
    gemm128_bias_relu<false><<<gemm_blocks_M, 512, GEMM_SMEM>>>(
        lx0, Wl, bl, local_x, nullptr, nullptr);

    const int spmm_blocks = 4096;

    for (int l = 0; l < L; l++) {
        // base graph propagation
        cudaMemsetAsync(base_agg, 0, (size_t)N * HH * sizeof(float));
        spmm_atomic<<<spmm_blocks, 256>>>(base_x, ei, ei + E, ew, base_agg, E);
        gemm128_bias_relu<false><<<gemm_blocks_N, 512, GEMM_SMEM>>>(
            base_agg, Wbase + (size_t)l * HH * HH, bbase + (size_t)l * HH, base_x,
            nullptr, nullptr);

        // local union-graph propagation + fused alpha-mix GEMM
        cudaMemsetAsync(local_agg, 0, (size_t)M * HH * sizeof(float));
        spmm_atomic<<<spmm_blocks, 256>>>(local_x, lei, lei + EL, lev, local_agg, EL);
        gemm128_bias_relu<true><<<gemm_blocks_M, 512, GEMM_SMEM>>>(
            local_agg, Wloc + (size_t)l * HH * HH, bloc + (size_t)l * HH, local_x,
            base_x, c2o);
    }

    // scatter-mean pooling + final projection
    cudaMemsetAsync(sub,  0, BB * HH * sizeof(float));
    cudaMemsetAsync(cntp, 0, BB * sizeof(float));
    const int pool_blocks = 128;
    const int entries_per_block = (K + pool_blocks - 1) / pool_blocks;
    pool_kernel<<<pool_blocks, 256>>>(local_x, midx, mgid, sub, cntp, K, entries_per_block);
    final_kernel<<<1, 128>>>(sub, cntp, Wp, bp, out);
}

// round 4
// speedup vs baseline: 1.7435x; 1.2851x over previous
#include <cuda_runtime.h>
#include <cstdint>

// ---------------- problem constants ----------------
#define NN   65536      // base nodes
#define MM   65536      // local nodes
#define HH   128        // hidden / feature dim
#define BB   64         // groups
#define OUTD 2
#define ALPHA 0.9f

// ---------------- device scratch (no runtime allocation allowed) ----------------
__device__ float g_base_x  [(size_t)NN * HH];
__device__ float g_base_agg[(size_t)NN * HH];
__device__ float g_local_x [(size_t)MM * HH];
__device__ float g_local_agg[(size_t)MM * HH];
__device__ float g_sub[BB * HH];
__device__ float g_cnt[BB];

// ---------------- GEMM: C[R x128] = relu(A'[R x128] @ W[128x128] + bias) ----------------
// A' = A                                   (MIX=false)
// A' = ALPHA*A + (1-ALPHA)*BX[c2o[row]]    (MIX=true, fused alpha-mix)
//
// 256 threads, 128x128 tile, 8 rows x 8 cols per thread (cols split 4 + 4,
// interleaved by 64 so each W LDS.128 is CONTIGUOUS across a quarter-warp ->
// conflict-free). Math = packed fma.rn.f32x2 (32 FFMA2 / thread / k).
// A smem uses an XOR swizzle on the row index (multiples of 8 only, driven by
// k's upper bits) to cut transpose-staging store conflicts 16-way -> 8-way
// while keeping mainloop reads 8-contiguous, 16B-aligned, warp-broadcast.
#define AS_LD 132
#define GEMM_SMEM ((128 * AS_LD + 128 * 128) * sizeof(float))   // 133120 B

__device__ __forceinline__ void ffma2(unsigned long long& d,
                                      unsigned long long a,
                                      unsigned long long b)
{
    asm("fma.rn.f32x2 %0, %1, %2, %0;" : "+l"(d) : "l"(a), "l"(b));
}

__device__ __forceinline__ unsigned long long dup_reg(float x)
{
    unsigned long long r;
    asm("mov.b64 %0, {%1, %1};" : "=l"(r) : "r"(__float_as_uint(x)));
    return r;
}

template<bool MIX>
__global__ void __launch_bounds__(256, 1)
gemm128_bias_relu(const float* __restrict__ A,
                  const float* __restrict__ W,
                  const float* __restrict__ bias,
                  float* __restrict__ C,
                  const float* __restrict__ BX,
                  const int* __restrict__ c2o)
{
    extern __shared__ float smem[];
    float* As = smem;                 // [128][AS_LD]  As[k][r ^ swz(k)]
    float* Ws = smem + 128 * AS_LD;   // [128][128]    Ws[k][col]

    const int tid  = threadIdx.x;
    const int row0 = blockIdx.x * 128;

    // ---- stage W (16384 floats = 4096 float4), 16 per thread, coalesced ----
    {
        const float4* W4  = (const float4*)W;
        float4*       Ws4 = (float4*)Ws;
        #pragma unroll
        for (int i = 0; i < 16; i++) Ws4[tid + 256 * i] = W4[tid + 256 * i];
    }
    // ---- stage A tile transposed + swizzled (optional fused alpha-mix) ----
    {
        const float4* A4 = (const float4*)(A + (size_t)row0 * HH);
        #pragma unroll
        for (int i = 0; i < 16; i++) {
            int idx = tid + 256 * i;      // = r*32 + k4 (warp: one row, lanes = k4)
            int r   = idx >> 5;
            int k4  = idx & 31;           // = lane
            float4 v = A4[idx];
            if (MIX) {
                int o = __ldg(&c2o[row0 + r]);
                float4 b = *(const float4*)&BX[(size_t)o * HH + k4 * 4];
                v.x = ALPHA * v.x + (1.0f - ALPHA) * b.x;
                v.y = ALPHA * v.y + (1.0f - ALPHA) * b.y;
                v.z = ALPHA * v.z + (1.0f - ALPHA) * b.z;
                v.w = ALPHA * v.w + (1.0f - ALPHA) * b.w;
            }
            // rows kk = 4*k4 + q, swizzled column = r ^ (8 * ((kk>>2)&15)) = r ^ (8*(k4&15))
            int rs = r ^ (8 * (k4 & 15));
            As[(4 * k4 + 0) * AS_LD + rs] = v.x;
            As[(4 * k4 + 1) * AS_LD + rs] = v.y;
            As[(4 * k4 + 2) * AS_LD + rs] = v.z;
            As[(4 * k4 + 3) * AS_LD + rs] = v.w;
        }
    }
    __syncthreads();

    const int j  = tid & 15;          // column group
    const int tr = (tid >> 4) * 8;    // row offset (0..120)
    const int c0 = 4 * j;             // cols c0..c0+3
    const int c1 = 64 + 4 * j;        // cols c1..c1+3

    // acc2[m][p]: row tr+m; p=0,1 -> col pairs (c0,c0+1),(c0+2,c0+3)
    //                       p=2,3 -> col pairs (c1,c1+1),(c1+2,c1+3)
    unsigned long long acc2[8][4];
    #pragma unroll
    for (int m = 0; m < 8; m++)
        #pragma unroll
        for (int p = 0; p < 4; p++) acc2[m][p] = 0ull;

    #pragma unroll 4
    for (int k = 0; k < 128; k++) {
        const int ab = tr ^ (8 * ((k >> 2) & 15));   // swizzled base, 8-contiguous
        float4 a0 = *(const float4*)&As[k * AS_LD + ab];       // rows tr..tr+3
        float4 a1 = *(const float4*)&As[k * AS_LD + ab + 4];   // rows tr+4..tr+7
        ulonglong2 w0 = *(const ulonglong2*)&Ws[k * 128 + c0]; // (wc0,wc0+1),(wc0+2,wc0+3)
        ulonglong2 w1 = *(const ulonglong2*)&Ws[k * 128 + c1];

        unsigned long long a2[8];
        a2[0] = dup_reg(a0.x); a2[1] = dup_reg(a0.y);
        a2[2] = dup_reg(a0.z); a2[3] = dup_reg(a0.w);
        a2[4] = dup_reg(a1.x); a2[5] = dup_reg(a1.y);
        a2[6] = dup_reg(a1.z); a2[7] = dup_reg(a1.w);
        unsigned long long wv[4] = {w0.x, w0.y, w1.x, w1.y};

        #pragma unroll
        for (int m = 0; m < 8; m++)
            #pragma unroll
            for (int p = 0; p < 4; p++)
                ffma2(acc2[m][p], a2[m], wv[p]);
    }

    float4 bv0 = *(const float4*)&bias[c0];
    float4 bv1 = *(const float4*)&bias[c1];

    #pragma unroll
    for (int m = 0; m < 8; m++) {
        float2 p0 = *(float2*)&acc2[m][0];
        float2 p1 = *(float2*)&acc2[m][1];
        float2 p2 = *(float2*)&acc2[m][2];
        float2 p3 = *(float2*)&acc2[m][3];
        float4 o0, o1;
        o0.x = fmaxf(p0.x + bv0.x, 0.f);
        o0.y = fmaxf(p0.y + bv0.y, 0.f);
        o0.z = fmaxf(p1.x + bv0.z, 0.f);
        o0.w = fmaxf(p1.y + bv0.w, 0.f);
        o1.x = fmaxf(p2.x + bv1.x, 0.f);
        o1.y = fmaxf(p2.y + bv1.y, 0.f);
        o1.z = fmaxf(p3.x + bv1.z, 0.f);
        o1.w = fmaxf(p3.y + bv1.w, 0.f);
        float* cp = &C[(size_t)(row0 + tr + m) * HH];
        *(float4*)&cp[c0] = o0;
        *(float4*)&cp[c1] = o1;
    }
}

// ---------------- SpMM scatter: Y[dst] += w * X[src], warp per edge ----------------
__global__ void spmm_atomic(const float* __restrict__ X,
                            const int* __restrict__ src,
                            const int* __restrict__ dst,
                            const float* __restrict__ wgt,
                            float* __restrict__ Y, int E)
{
    const int lane   = threadIdx.x & 31;
    const int warp   = (blockIdx.x * blockDim.x + threadIdx.x) >> 5;
    const int nwarps = (gridDim.x * blockDim.x) >> 5;
    for (int e = warp; e < E; e += nwarps) {
        int   s = src[e];
        int   d = dst[e];
        float w = wgt[e];
        float4 v = *(const float4*)&X[(size_t)s * HH + lane * 4];
        v.x *= w; v.y *= w; v.z *= w; v.w *= w;
        float* p = &Y[(size_t)d * HH + lane * 4];
        asm volatile("red.global.add.v4.f32 [%0], {%1, %2, %3, %4};"
                     :: "l"(p), "f"(v.x), "f"(v.y), "f"(v.z), "f"(v.w)
                     : "memory");
    }
}

// ---------------- pooling: two-stage segment-sum into g_sub / g_cnt ----------------
__global__ void pool_kernel(const float* __restrict__ lx,
                            const int* __restrict__ midx,
                            const int* __restrict__ mgid,
                            float* __restrict__ gsub,
                            float* __restrict__ gcnt,
                            int K, int entries_per_block)
{
    __shared__ float acc[BB * HH];   // 32 KB
    __shared__ float cnt[BB];
    const int tid = threadIdx.x;
    for (int i = tid; i < BB * HH; i += blockDim.x) acc[i] = 0.f;
    if (tid < BB) cnt[tid] = 0.f;
    __syncthreads();

    const int warp = tid >> 5;
    const int lane = tid & 31;
    const int base = blockIdx.x * entries_per_block;
    const int end  = min(base + entries_per_block, K);
    for (int k = base + warp; k < end; k += (int)(blockDim.x >> 5)) {
        int idx = midx[k];
        int g   = mgid[k];
        float4 v = *(const float4*)&lx[(size_t)idx * HH + lane * 4];
        atomicAdd(&acc[g * HH + lane * 4 + 0], v.x);
        atomicAdd(&acc[g * HH + lane * 4 + 1], v.y);
        atomicAdd(&acc[g * HH + lane * 4 + 2], v.z);
        atomicAdd(&acc[g * HH + lane * 4 + 3], v.w);
        if (lane == 0) atomicAdd(&cnt[g], 1.f);
    }
    __syncthreads();

    for (int i = tid; i < BB * HH; i += blockDim.x)
        if (acc[i] != 0.f) atomicAdd(&gsub[i], acc[i]);
    if (tid < BB && cnt[tid] != 0.f) atomicAdd(&gcnt[tid], cnt[tid]);
}

// ---------------- final: out[b][o] = (sub[b]/max(cnt,1)) @ Wp + bp ----------------
__global__ void final_kernel(const float* __restrict__ gsub,
                             const float* __restrict__ gcnt,
                             const float* __restrict__ Wp,
                             const float* __restrict__ bp,
                             float* __restrict__ out)
{
    int t = threadIdx.x;                 // 0..127
    if (t >= BB * OUTD) return;
    int b = t >> 1, o = t & 1;
    float c = fmaxf(gcnt[b], 1.f);
    float s = 0.f;
    #pragma unroll 8
    for (int h = 0; h < HH; h++) s = fmaf(gsub[b * HH + h], Wp[h * OUTD + o], s);
    out[t] = s / c + bp[o];
}

// ---------------- host orchestration ----------------
extern "C" void kernel_launch(void* const* d_in, const int* in_sizes, int n_in,
                              void* d_out, int out_size)
{
    const float* x    = (const float*)d_in[0];
    const int*   ei   = (const int*)  d_in[1];
    const float* ew   = (const float*)d_in[2];
    const float* lx0  = (const float*)d_in[3];
    const int*   c2o  = (const int*)  d_in[4];
    const int*   lei  = (const int*)  d_in[5];
    const float* lev  = (const float*)d_in[6];
    const int*   midx = (const int*)  d_in[7];
    const int*   mgid = (const int*)  d_in[8];
    // d_in[9] = B (scalar) -- fixed at 64
    const float* Wb    = (const float*)d_in[10];
    const float* bb    = (const float*)d_in[11];
    const float* Wl    = (const float*)d_in[12];
    const float* bl    = (const float*)d_in[13];
    const float* Wbase = (const float*)d_in[14];
    const float* bbase = (const float*)d_in[15];
    const float* Wloc  = (const float*)d_in[16];
    const float* bloc  = (const float*)d_in[17];
    const float* Wp    = (const float*)d_in[18];
    const float* bp    = (const float*)d_in[19];
    float* out = (float*)d_out;

    const int N  = in_sizes[0] / HH;
    const int M  = in_sizes[3] / HH;
    const int E  = in_sizes[1] / 2;
    const int EL = in_sizes[5] / 2;
    const int K  = in_sizes[7];
    const int L  = in_sizes[14] / (HH * HH);

    float *base_x, *base_agg, *local_x, *local_agg, *sub, *cntp;
    cudaGetSymbolAddress((void**)&base_x,   g_base_x);
    cudaGetSymbolAddress((void**)&base_agg, g_base_agg);
    cudaGetSymbolAddress((void**)&local_x,  g_local_x);
    cudaGetSymbolAddress((void**)&local_agg,g_local_agg);
    cudaGetSymbolAddress((void**)&sub,      g_sub);
    cudaGetSymbolAddress((void**)&cntp,     g_cnt);

    cudaFuncSetAttribute(gemm128_bias_relu<false>,
                         cudaFuncAttributeMaxDynamicSharedMemorySize, (int)GEMM_SMEM);
    cudaFuncSetAttribute(gemm128_bias_relu<true>,
                         cudaFuncAttributeMaxDynamicSharedMemorySize, (int)GEMM_SMEM);

    const int gemm_blocks_N = N / 128;
    const int gemm_blocks_M = M / 128;

    // input projections
    gemm128_bias_relu<false><<<gemm_blocks_N, 256, GEMM_SMEM>>>(
        x,   Wb, bb, base_x, nullptr, nullptr);
    gemm128_bias_relu<false><<<gemm_blocks_M, 256, GEMM_SMEM>>>(
        lx0, Wl, bl, local_x, nullptr, nullptr);

    const int spmm_blocks = 4096;

    for (int l = 0; l < L; l++) {
        // base graph propagation
        cudaMemsetAsync(base_agg, 0, (size_t)N * HH * sizeof(float));
        spmm_atomic<<<spmm_blocks, 256>>>(base_x, ei, ei + E, ew, base_agg, E);
        gemm128_bias_relu<false><<<gemm_blocks_N, 256, GEMM_SMEM>>>(
            base_agg, Wbase + (size_t)l * HH * HH, bbase + (size_t)l * HH, base_x,
            nullptr, nullptr);

        // local union-graph propagation + fused alpha-mix GEMM
        cudaMemsetAsync(local_agg, 0, (size_t)M * HH * sizeof(float));
        spmm_atomic<<<spmm_blocks, 256>>>(local_x, lei, lei + EL, lev, local_agg, EL);
        gemm128_bias_relu<true><<<gemm_blocks_M, 256, GEMM_SMEM>>>(
            local_agg, Wloc + (size_t)l * HH * HH, bloc + (size_t)l * HH, local_x,
            base_x, c2o);
    }

    // scatter-mean pooling + final projection
    cudaMemsetAsync(sub,  0, BB * HH * sizeof(float));
    cudaMemsetAsync(cntp, 0, BB * sizeof(float));
    const int pool_blocks = 128;
    const int entries_per_block = (K + pool_blocks - 1) / pool_blocks;
    pool_kernel<<<pool_blocks, 256>>>(local_x, midx, mgid, sub, cntp, K, entries_per_block);
    final_kernel<<<1, 128>>>(sub, cntp, Wp, bp, out);
}